// round 1
// baseline (speedup 1.0000x reference)
#include <cuda_runtime.h>

#define N_NODES  50000
#define HID      128
#define IN_DIM   64
#define OUT_DIM  10
#define N_GRAPHS 64

// ---------------- scratch (static device globals; no allocation) -------------
__device__ float g_hs[(size_t)N_NODES * HID];   // dinv * (X @ W^T)
__device__ float g_acc[(size_t)N_NODES * HID];  // edge scatter accumulator / h1
__device__ float g_deg[N_NODES];                // deg -> dinv (in place)
__device__ float g_pool[N_GRAPHS * HID];
__device__ float g_cnt[N_GRAPHS];

// ---------------- small kernels ----------------------------------------------
__global__ void init_kernel() {
    int i = blockIdx.x * blockDim.x + threadIdx.x;
    if (i < N_NODES) g_deg[i] = 1.0f;           // self-loop contributes 1
    if (i < N_GRAPHS * HID) g_pool[i] = 0.0f;
    if (i < N_GRAPHS) g_cnt[i] = 0.0f;
}

__global__ void degree_kernel(const int* __restrict__ ei, int E) {
    int i = blockIdx.x * blockDim.x + threadIdx.x;
    if (i < E) atomicAdd(&g_deg[ei[E + i]], 1.0f);   // dst row
}

__global__ void rsqrt_kernel() {
    int i = blockIdx.x * blockDim.x + threadIdx.x;
    if (i < N_NODES) g_deg[i] = rsqrtf(g_deg[i]);    // deg >= 1 always
}

__global__ void zero_acc_kernel() {
    size_t n = (size_t)N_NODES * HID / 4;
    float4* p = (float4*)g_acc;
    float4 z = make_float4(0.f, 0.f, 0.f, 0.f);
    for (size_t i = blockIdx.x * blockDim.x + threadIdx.x; i < n;
         i += (size_t)gridDim.x * blockDim.x)
        p[i] = z;
}

// ---------------- GEMM: g_hs[n][c] = dinv[n] * sum_k X[n][k] * W[c][k] --------
// Tile: 32 rows x 128 cols per block, 256 threads, 4x4 register blocking,
// K chunked by 64 so smem fits statically for both K=64 and K=128.
template <int K, bool USE_ACC>
__global__ void __launch_bounds__(256) gemm_kernel(const float* __restrict__ X,
                                                   const float* __restrict__ W) {
    __shared__ float ws[64][132];  // [k][c], padded (132 = 4*33, 16B aligned rows)
    __shared__ float xs[64][36];   // [k][r], padded

    const float* __restrict__ Xp = USE_ACC ? (const float*)g_acc : X;

    int tid = threadIdx.x;
    int tr = tid >> 5;      // 0..7 : row group
    int tc = tid & 31;      // 0..31: col group
    int row0 = blockIdx.x * 32;

    float acc[4][4] = {};

    for (int kc = 0; kc < K; kc += 64) {
        // load W chunk [128 x 64] -> ws[k][c]
        for (int i = tid; i < 128 * 64; i += 256) {
            int c = i >> 6;
            int k = i & 63;
            ws[k][c] = W[c * K + kc + k];
        }
        // load X chunk [32 x 64] -> xs[k][r]
        for (int i = tid; i < 32 * 64; i += 256) {
            int r = i >> 6;
            int k = i & 63;
            int row = row0 + r;
            xs[k][r] = (row < N_NODES) ? Xp[(size_t)row * K + kc + k] : 0.0f;
        }
        __syncthreads();

#pragma unroll 16
        for (int k = 0; k < 64; k++) {
            float4 a = *(const float4*)&xs[k][tr * 4];
            float4 b = *(const float4*)&ws[k][tc * 4];
            acc[0][0] += a.x * b.x; acc[0][1] += a.x * b.y;
            acc[0][2] += a.x * b.z; acc[0][3] += a.x * b.w;
            acc[1][0] += a.y * b.x; acc[1][1] += a.y * b.y;
            acc[1][2] += a.y * b.z; acc[1][3] += a.y * b.w;
            acc[2][0] += a.z * b.x; acc[2][1] += a.z * b.y;
            acc[2][2] += a.z * b.z; acc[2][3] += a.z * b.w;
            acc[3][0] += a.w * b.x; acc[3][1] += a.w * b.y;
            acc[3][2] += a.w * b.z; acc[3][3] += a.w * b.w;
        }
        __syncthreads();
    }

#pragma unroll
    for (int i = 0; i < 4; i++) {
        int row = row0 + tr * 4 + i;
        if (row < N_NODES) {
            float dv = g_deg[row];
            float4 v = make_float4(acc[i][0] * dv, acc[i][1] * dv,
                                   acc[i][2] * dv, acc[i][3] * dv);
            *(float4*)&g_hs[(size_t)row * HID + tc * 4] = v;
        }
    }
}

// ---------------- edge scatter: acc[dst] += hs[src] (vector atomics) ---------
__global__ void scatter_kernel(const int* __restrict__ ei, int E) {
    int gwarp = (blockIdx.x * blockDim.x + threadIdx.x) >> 5;
    int lane = threadIdx.x & 31;
    int nwarps = (gridDim.x * blockDim.x) >> 5;
    for (int e = gwarp; e < E; e += nwarps) {
        int s = __ldg(ei + e);
        int d = __ldg(ei + E + e);
        const float4 v = *(const float4*)(g_hs + (size_t)s * HID + lane * 4);
        float* dst = g_acc + (size_t)d * HID + lane * 4;
        asm volatile("red.global.add.v4.f32 [%0], {%1, %2, %3, %4};"
                     :: "l"(dst), "f"(v.x), "f"(v.y), "f"(v.z), "f"(v.w)
                     : "memory");
    }
}

// ---------------- post layer 1: acc = relu(dinv*(acc + hs) + b) --------------
__global__ void post1_kernel(const float* __restrict__ b) {
    int idx = blockIdx.x * blockDim.x + threadIdx.x;
    if (idx >= N_NODES * 32) return;
    int n = idx >> 5, q = idx & 31;
    float4 a = ((const float4*)g_acc)[idx];
    float4 h = ((const float4*)g_hs)[idx];
    float4 bb = ((const float4*)b)[q];
    float dv = g_deg[n];
    float4 r;
    r.x = fmaxf(dv * (a.x + h.x) + bb.x, 0.0f);
    r.y = fmaxf(dv * (a.y + h.y) + bb.y, 0.0f);
    r.z = fmaxf(dv * (a.z + h.z) + bb.z, 0.0f);
    r.w = fmaxf(dv * (a.w + h.w) + bb.w, 0.0f);
    ((float4*)g_acc)[idx] = r;
}

// ---------------- post layer 2 + mean-pool accumulation ----------------------
__global__ void post2_kernel(const float* __restrict__ b,
                             const int* __restrict__ batch) {
    int idx = blockIdx.x * blockDim.x + threadIdx.x;
    if (idx >= N_NODES * 32) return;
    int n = idx >> 5, q = idx & 31;
    float4 a = ((const float4*)g_acc)[idx];
    float4 h = ((const float4*)g_hs)[idx];
    float4 bb = ((const float4*)b)[q];
    float dv = g_deg[n];
    float4 r;
    r.x = fmaxf(dv * (a.x + h.x) + bb.x, 0.0f);
    r.y = fmaxf(dv * (a.y + h.y) + bb.y, 0.0f);
    r.z = fmaxf(dv * (a.z + h.z) + bb.z, 0.0f);
    r.w = fmaxf(dv * (a.w + h.w) + bb.w, 0.0f);
    int g = __ldg(batch + n);
    float* dst = g_pool + (size_t)g * HID + q * 4;
    asm volatile("red.global.add.v4.f32 [%0], {%1, %2, %3, %4};"
                 :: "l"(dst), "f"(r.x), "f"(r.y), "f"(r.z), "f"(r.w)
                 : "memory");
    if (q == 0) atomicAdd(&g_cnt[g], 1.0f);
}

// ---------------- final: out[g][o] = pooled[g] . fc_w[o] + fc_b[o] -----------
__global__ void final_kernel(const float* __restrict__ fcw,
                             const float* __restrict__ fcb,
                             float* __restrict__ out) {
    int g = blockIdx.x;
    int lane = threadIdx.x;
    float inv = 1.0f / fmaxf(g_cnt[g], 1.0f);
    float p[4];
#pragma unroll
    for (int j = 0; j < 4; j++) p[j] = g_pool[g * HID + j * 32 + lane] * inv;
#pragma unroll
    for (int o = 0; o < OUT_DIM; o++) {
        float s = 0.0f;
#pragma unroll
        for (int j = 0; j < 4; j++) s += p[j] * fcw[o * HID + j * 32 + lane];
#pragma unroll
        for (int off = 16; off; off >>= 1) s += __shfl_down_sync(0xFFFFFFFFu, s, off);
        if (lane == 0) out[g * OUT_DIM + o] = s + fcb[o];
    }
}

// ---------------- launch ------------------------------------------------------
extern "C" void kernel_launch(void* const* d_in, const int* in_sizes, int n_in,
                              void* d_out, int out_size) {
    const float* x    = (const float*)d_in[0];
    const int*   ei   = (const int*)  d_in[1];
    const int*   batch= (const int*)  d_in[2];
    const float* w1   = (const float*)d_in[3];
    const float* b1   = (const float*)d_in[4];
    const float* w2   = (const float*)d_in[5];
    const float* b2   = (const float*)d_in[6];
    const float* fcw  = (const float*)d_in[7];
    const float* fcb  = (const float*)d_in[8];
    float* out = (float*)d_out;
    int E = in_sizes[1] / 2;

    int nblk = (N_NODES + 255) / 256;
    init_kernel<<<nblk, 256>>>();
    degree_kernel<<<(E + 255) / 256, 256>>>(ei, E);
    rsqrt_kernel<<<nblk, 256>>>();

    int gemm_blocks = (N_NODES + 31) / 32;
    // layer 1
    gemm_kernel<IN_DIM, false><<<gemm_blocks, 256>>>(x, w1);
    zero_acc_kernel<<<1024, 256>>>();
    scatter_kernel<<<4096, 256>>>(ei, E);
    post1_kernel<<<(N_NODES * 32 + 255) / 256, 256>>>(b1);
    // layer 2
    gemm_kernel<HID, true><<<gemm_blocks, 256>>>(nullptr, w2);
    zero_acc_kernel<<<1024, 256>>>();
    scatter_kernel<<<4096, 256>>>(ei, E);
    post2_kernel<<<(N_NODES * 32 + 255) / 256, 256>>>(b2, batch);

    final_kernel<<<N_GRAPHS, 32>>>(fcw, fcb, out);
}